// round 7
// baseline (speedup 1.0000x reference)
#include <cuda_runtime.h>
#include <math.h>

typedef unsigned long long ull;

#define TT 2048
#define BB 64
#define II 128
#define HH 256
#define NBLK 128            /* 16 clusters x 8 CTAs */
#define CLUS 8
#define NTHR 512
#define HXS  68             /* gx-kernel x staging row stride */
#define HBS  12             /* hb row stride: 48B = conflict-free + 16B aligned */

// ---- device scratch (static) ----
__device__ __align__(16) float g_xT[(size_t)TT * II * BB];       // [t][i][b]
__device__ __align__(16) float g_gx[(size_t)TT * BB * HH * 4];   // [t][b][j][g]

// ---- helpers ----
__device__ __forceinline__ void cp16(float* smem_dst, const float* gmem_src) {
    unsigned s = (unsigned)__cvta_generic_to_shared(smem_dst);
    asm volatile("cp.async.cg.shared.global [%0], [%1], 16;" :: "r"(s), "l"(gmem_src));
}
#define CP_COMMIT() asm volatile("cp.async.commit_group;" ::: "memory")
#define CP_WAIT0()  asm volatile("cp.async.wait_group 0;" ::: "memory")

__device__ __forceinline__ ull pk2(float v) {
    ull r; unsigned u = __float_as_uint(v);
    asm("mov.b64 %0, {%1, %1};" : "=l"(r) : "r"(u));
    return r;
}
__device__ __forceinline__ ull pkab(float a, float b) {
    ull r; unsigned ua = __float_as_uint(a), ub = __float_as_uint(b);
    asm("mov.b64 %0, {%1, %2};" : "=l"(r) : "r"(ua), "r"(ub));
    return r;
}
__device__ __forceinline__ void fma2(ull& d, ull a, ull b) {
    asm("fma.rn.f32x2 %0, %1, %2, %0;" : "+l"(d) : "l"(a), "l"(b));
}
__device__ __forceinline__ ull add2(ull a, ull b) {
    ull r; asm("add.rn.f32x2 %0, %1, %2;" : "=l"(r) : "l"(a), "l"(b));
    return r;
}
__device__ __forceinline__ unsigned smem_u32(const void* p) {
    unsigned a;
    asm("{ .reg .u64 t; cvta.to.shared.u64 t, %1; cvt.u32.u64 %0, t; }"
        : "=r"(a) : "l"(p));
    return a;
}
__device__ __forceinline__ unsigned mapa_rank(unsigned laddr, unsigned rank) {
    unsigned r;
    asm("mapa.shared::cluster.u32 %0, %1, %2;" : "=r"(r) : "r"(laddr), "r"(rank));
    return r;
}
#define CLUSTER_ARRIVE() asm volatile("barrier.cluster.arrive.aligned;" ::: "memory")
#define CLUSTER_WAIT()   asm volatile("barrier.cluster.wait.aligned;" ::: "memory")

// ============================================================
// Kernel 1: transpose x [b][t][i] -> g_xT [t][i][b]
// ============================================================
__global__ void __launch_bounds__(256) xpose_kernel(const float* __restrict__ x)
{
    __shared__ float xs[BB * (II + 1)];
    const int t = blockIdx.x;
    for (int idx = threadIdx.x; idx < BB * II; idx += 256) {
        int b = idx >> 7, i = idx & 127;
        xs[b * (II + 1) + i] = x[((size_t)b * TT + t) * II + i];
    }
    __syncthreads();
    float* dst = g_xT + (size_t)t * (II * BB);
    for (int idx = threadIdx.x; idx < II * BB; idx += 256) {
        int i = idx >> 6, b = idx & 63;
        dst[idx] = xs[b * (II + 1) + i];
    }
}

// ============================================================
// Kernel 2: precompute gx[t][b][j][g] = (x_t . W_x)
// grid (t=2048, cb=8): cb covers h-cols 32cb..32cb+31 (x 4 gates).
// ============================================================
#define GX_XS 0
#define GX_WS (II * HXS)
#define GX_SMEM_FLOATS (GX_WS + II * 128)
#define GX_SMEM_BYTES  (GX_SMEM_FLOATS * 4)

__global__ void __launch_bounds__(512) gx_kernel(const float* __restrict__ Wx)
{
    extern __shared__ float sm[];
    float* xs  = sm + GX_XS;
    float* ws2 = sm + GX_WS;

    const int t    = blockIdx.x;
    const int cb   = blockIdx.y;
    const int tid  = threadIdx.x;
    const int lane = tid & 31;
    const int bq   = tid >> 5;

    {
        const float* src = g_xT + (size_t)t * (II * BB);
        #pragma unroll
        for (int i = 0; i < 4; ++i) {
            int idx = tid + i * 512;
            int row = idx >> 4, c4 = (idx & 15) << 2;
            cp16(xs + row * HXS + c4, src + idx * 4);
        }
        CP_COMMIT();
    }
    #pragma unroll
    for (int j = 0; j < 32; ++j) {
        int idx = tid + j * 512;
        int k = idx >> 7, rem = idx & 127;
        int g = rem >> 5, hl = rem & 31;
        ws2[k * 128 + hl * 4 + g] = __ldg(Wx + ((size_t)g * II + k) * HH + (cb << 5) + hl);
    }
    CP_WAIT0();
    __syncthreads();

    ull acc2[8];
    #pragma unroll
    for (int i = 0; i < 8; ++i) acc2[i] = 0ull;

    const float* xp = xs + (bq << 2);
    const float* wp = ws2 + (lane << 2);
    #pragma unroll 4
    for (int k = 0; k < II; ++k) {
        float4 hv = *(const float4*)(xp + k * HXS);
        ulonglong2 wv = *(const ulonglong2*)(wp + k * 128);
        ull h0 = pk2(hv.x), h1 = pk2(hv.y), h2 = pk2(hv.z), h3 = pk2(hv.w);
        fma2(acc2[0], h0, wv.x); fma2(acc2[1], h0, wv.y);
        fma2(acc2[2], h1, wv.x); fma2(acc2[3], h1, wv.y);
        fma2(acc2[4], h2, wv.x); fma2(acc2[5], h2, wv.y);
        fma2(acc2[6], h3, wv.x); fma2(acc2[7], h3, wv.y);
    }

    #pragma unroll
    for (int r = 0; r < 4; ++r) {
        int b = (bq << 2) + r;
        ulonglong2 v; v.x = acc2[r * 2]; v.y = acc2[r * 2 + 1];
        *(ulonglong2*)(g_gx + (((size_t)t * BB + b) * HH + (cb << 5) + lane) * 4) = v;
    }
}

// ============================================================
// Kernel 3: clustered LSTM recurrence, weights in registers,
// h pre-duplicated in SMEM, mbarrier producer/consumer pipeline.
// 16 clusters x 8 CTAs; cluster cid owns batches 4cid..4cid+3.
// CTA rank r owns h-outputs j in [32r, 32r+32) (local col = jl*4 + g).
// Warp w: cols 8w..8w+7, all 4 batches. Lane: k-slice {lane+32u}.
// SMEM: hb[2][256][12] (h duplicated pairs, 48B rows) + mbar[2].
// ============================================================
__global__ void __launch_bounds__(NTHR, 1) __cluster_dims__(CLUS, 1, 1)
lstm_kernel(const float* __restrict__ Wh, const float* __restrict__ bias,
            float* __restrict__ out)
{
    __shared__ __align__(16) float hb[2][HH][HBS];  // [buf][k][2b..2b+1 dup]
    __shared__ __align__(8) ull mbar[2];

    const int tid  = threadIdx.x;
    const int w    = tid >> 5;
    const int lane = tid & 31;
    unsigned rank;
    asm("mov.u32 %0, %%cluster_ctarank;" : "=r"(rank));
    const int cid = blockIdx.x >> 3;

    const unsigned mb0 = smem_u32(&mbar[0]);
    const unsigned mb1 = smem_u32(&mbar[1]);
    const unsigned hb_u = smem_u32(hb);

    if (tid == 0) {
        asm volatile("mbarrier.init.shared.b64 [%0], %1;" :: "r"(mb0), "r"(CLUS) : "memory");
        asm volatile("mbarrier.init.shared.b64 [%0], %1;" :: "r"(mb1), "r"(CLUS) : "memory");
    }
    __syncthreads();
    CLUSTER_ARRIVE(); CLUSTER_WAIT();   // mbarrier inits visible cluster-wide

    // ---- one-time: W_h slice into 64 registers (packed col-pairs) ----
    // wreg[u*4+p] = pack(Wh[.][k][colpair]) matching acc2 layout of R6.
    ull wreg[32];
    #pragma unroll
    for (int u = 0; u < 8; ++u) {
        const int k = lane + (u << 5);
        #pragma unroll
        for (int p = 0; p < 4; ++p) {
            const int c0 = (w << 3) + (p << 1), c1 = c0 + 1;
            const int jj0 = (int)(rank << 5) + (c0 >> 2), gg0 = c0 & 3;
            const int jj1 = (int)(rank << 5) + (c1 >> 2), gg1 = c1 & 3;
            float f0 = __ldg(Wh + ((size_t)gg0 * HH + k) * HH + jj0);
            float f1 = __ldg(Wh + ((size_t)gg1 * HH + k) * HH + jj1);
            wreg[(u << 2) + p] = pkab(f0, f1);
        }
    }

    const int  col  = (w << 3) + (lane & 7);
    const int  b_l  = lane >> 3;
    const int  j    = (int)(rank << 5) + (col >> 2);
    const int  gg_  = col & 3;
    const int  bse  = lane & 28;
    const bool upd  = (lane & 3) == 0;
    const float biasv = __ldg(bias + (size_t)gg_ * HH + j);
    const int  myb  = (cid << 2) + b_l;
    const float* gxp = g_gx + (((size_t)myb * HH + j) << 2) + gg_;

    float creg = 0.f;

    for (int t = 0; t < TT; ++t) {
        float gxv = __ldg(gxp + (size_t)t * (BB * HH * 4));  // issued before wait

        ull acc2[16];
        #pragma unroll
        for (int i = 0; i < 16; ++i) acc2[i] = 0ull;

        if (t > 0) {
            // ---- consumer wait: mbar[t&1], parity ((t-1)>>1)&1, acquire.cluster ----
            {
                unsigned mb = (t & 1) ? mb1 : mb0;
                unsigned par = (unsigned)((t - 1) >> 1) & 1u;
                unsigned done;
                asm volatile(
                    "{\n\t.reg .pred p;\n\t"
                    "mbarrier.try_wait.parity.acquire.cluster.shared::cta.b64 p, [%1], %2, 0x989680;\n\t"
                    "selp.b32 %0, 1, 0, p;\n\t}"
                    : "=r"(done) : "r"(mb), "r"(par) : "memory");
                while (!done) {
                    asm volatile(
                        "{\n\t.reg .pred p;\n\t"
                        "mbarrier.try_wait.parity.acquire.cluster.shared::cta.b64 p, [%1], %2, 0x989680;\n\t"
                        "selp.b32 %0, 1, 0, p;\n\t}"
                        : "=r"(done) : "r"(mb), "r"(par) : "memory");
                }
            }
            // ---- h-part: FFMA2 from register weights + duplicated-h LDS ----
            const char* hrow = (const char*)hb + ((t & 1) ? (HH * HBS * 4) : 0)
                             + lane * (HBS * 4);
            #pragma unroll
            for (int u = 0; u < 8; ++u) {
                ulonglong2 hx01 = *(const ulonglong2*)(hrow + u * (32 * HBS * 4));
                ulonglong2 hx23 = *(const ulonglong2*)(hrow + u * (32 * HBS * 4) + 16);
                fma2(acc2[0],  hx01.x, wreg[(u << 2) + 0]);
                fma2(acc2[1],  hx01.x, wreg[(u << 2) + 1]);
                fma2(acc2[2],  hx01.x, wreg[(u << 2) + 2]);
                fma2(acc2[3],  hx01.x, wreg[(u << 2) + 3]);
                fma2(acc2[4],  hx01.y, wreg[(u << 2) + 0]);
                fma2(acc2[5],  hx01.y, wreg[(u << 2) + 1]);
                fma2(acc2[6],  hx01.y, wreg[(u << 2) + 2]);
                fma2(acc2[7],  hx01.y, wreg[(u << 2) + 3]);
                fma2(acc2[8],  hx23.x, wreg[(u << 2) + 0]);
                fma2(acc2[9],  hx23.x, wreg[(u << 2) + 1]);
                fma2(acc2[10], hx23.x, wreg[(u << 2) + 2]);
                fma2(acc2[11], hx23.x, wreg[(u << 2) + 3]);
                fma2(acc2[12], hx23.y, wreg[(u << 2) + 0]);
                fma2(acc2[13], hx23.y, wreg[(u << 2) + 1]);
                fma2(acc2[14], hx23.y, wreg[(u << 2) + 2]);
                fma2(acc2[15], hx23.y, wreg[(u << 2) + 3]);
            }
        }

        // ---- packed butterfly reduce-scatter (same order as R5/R6) ----
        #pragma unroll
        for (int n = 16; n >= 2; n >>= 1) {
            const int m = n >> 1;
            #pragma unroll
            for (int s = 0; s < m; ++s) {
                ull lo = acc2[s], hi = acc2[s + m];
                ull send = (lane & n) ? lo : hi;
                ull keep = (lane & n) ? hi : lo;
                acc2[s] = add2(keep, __shfl_xor_sync(0xffffffffu, send, n));
            }
        }
        float pre;
        {
            unsigned u0, u1;
            asm("mov.b64 {%0, %1}, %2;" : "=r"(u0), "=r"(u1) : "l"(acc2[0]));
            float a0 = __uint_as_float(u0), a1 = __uint_as_float(u1);
            float send = (lane & 1) ? a0 : a1;
            float keep = (lane & 1) ? a1 : a0;
            pre = keep + __shfl_xor_sync(0xffffffffu, send, 1);
        }
        pre += gxv + biasv;

        // ---- gather 4 gates, cell update, push h to all 8 CTAs ----
        float pf = __shfl_sync(0xffffffffu, pre, bse | 1);
        float pg = __shfl_sync(0xffffffffu, pre, bse | 2);
        float po = __shfl_sync(0xffffffffu, pre, bse | 3);
        if (upd) {
            float ig = 1.f / (1.f + __expf(-pre));
            float fg = 1.f / (1.f + __expf(-pf));
            float gv = tanhf(pg);
            float og = 1.f / (1.f + __expf(-po));
            creg = fg * creg + ig * gv;
            float hv = og * tanhf(creg);
            if (t + 1 < TT) {
                ull hd = pk2(hv);
                unsigned dst = ((unsigned)((t & 1) ^ 1)) * (HH * HBS * 4)
                             + (unsigned)j * (HBS * 4) + ((unsigned)b_l << 3);
                #pragma unroll
                for (int r = 0; r < CLUS; ++r) {
                    unsigned ra = mapa_rank(hb_u, (unsigned)r) + dst;
                    asm volatile("st.shared::cluster.u64 [%0], %1;"
                                 :: "r"(ra), "l"(hd) : "memory");
                }
            }
            out[((size_t)myb * TT + t) * HH + j] = hv;
        }

        __syncthreads();   // all upd stores issued before the release below
        if (t + 1 < TT && tid == 0) {
            asm volatile("fence.acq_rel.cluster;" ::: "memory");
            unsigned mbn = ((t + 1) & 1) ? mb1 : mb0;
            #pragma unroll
            for (int r = 0; r < CLUS; ++r) {
                unsigned ra = mapa_rank(mbn, (unsigned)r);
                asm volatile("mbarrier.arrive.release.cluster.shared::cluster.b64 _, [%0];"
                             :: "r"(ra) : "memory");
            }
        }
    }

    CLUSTER_ARRIVE(); CLUSTER_WAIT();   // no early exit while peers may store into us
}

// ============================================================
extern "C" void kernel_launch(void* const* d_in, const int* in_sizes, int n_in,
                              void* d_out, int out_size)
{
    const float* x  = (const float*)d_in[0];   // [B, T, I]
    const float* Wx = (const float*)d_in[1];   // [4, I, H]
    const float* Wh = (const float*)d_in[2];   // [4, H, H]
    const float* b  = (const float*)d_in[3];   // [4, H]
    float* out = (float*)d_out;                // [B, T, H]

    cudaFuncSetAttribute(gx_kernel,
                         cudaFuncAttributeMaxDynamicSharedMemorySize, GX_SMEM_BYTES);

    xpose_kernel<<<TT, 256>>>(x);
    gx_kernel<<<dim3(TT, 8), 512, GX_SMEM_BYTES>>>(Wx);
    lstm_kernel<<<NBLK, NTHR>>>(Wh, b, out);
}

// round 8
// speedup vs baseline: 1.2231x; 1.2231x over previous
#include <cuda_runtime.h>
#include <math.h>

typedef unsigned long long ull;

#define TT 2048
#define BB 64
#define II 128
#define HH 256
#define NBLK 128            /* 16 clusters x 8 CTAs */
#define CLUS 8
#define NTHR 1024
#define HXS  68             /* gx-kernel x staging row stride */
#define WST  132            /* W_h slice row stride (128 cols + 4 pad) */

// ---- device scratch (static) ----
__device__ __align__(16) float g_xT[(size_t)TT * II * BB];       // [t][i][b]
__device__ __align__(16) float g_gx[(size_t)TT * BB * HH * 4];   // [t][b][j][g]

// ---- helpers ----
__device__ __forceinline__ void cp16(float* smem_dst, const float* gmem_src) {
    unsigned s = (unsigned)__cvta_generic_to_shared(smem_dst);
    asm volatile("cp.async.cg.shared.global [%0], [%1], 16;" :: "r"(s), "l"(gmem_src));
}
#define CP_COMMIT() asm volatile("cp.async.commit_group;" ::: "memory")
#define CP_WAIT0()  asm volatile("cp.async.wait_group 0;" ::: "memory")

__device__ __forceinline__ ull pk2(float v) {
    ull r; unsigned u = __float_as_uint(v);
    asm("mov.b64 %0, {%1, %1};" : "=l"(r) : "r"(u));
    return r;
}
__device__ __forceinline__ void fma2(ull& d, ull a, ull b) {
    asm("fma.rn.f32x2 %0, %1, %2, %0;" : "+l"(d) : "l"(a), "l"(b));
}
__device__ __forceinline__ ull add2(ull a, ull b) {
    ull r; asm("add.rn.f32x2 %0, %1, %2;" : "=l"(r) : "l"(a), "l"(b));
    return r;
}
__device__ __forceinline__ unsigned smem_u32(const void* p) {
    unsigned a;
    asm("{ .reg .u64 t; cvta.to.shared.u64 t, %1; cvt.u32.u64 %0, t; }"
        : "=r"(a) : "l"(p));
    return a;
}
__device__ __forceinline__ unsigned mapa_rank(unsigned laddr, unsigned rank) {
    unsigned r;
    asm("mapa.shared::cluster.u32 %0, %1, %2;" : "=r"(r) : "r"(laddr), "r"(rank));
    return r;
}
#define CLUSTER_ARRIVE() asm volatile("barrier.cluster.arrive.aligned;" ::: "memory")
#define CLUSTER_WAIT()   asm volatile("barrier.cluster.wait.aligned;" ::: "memory")

// ============================================================
// Kernel 1: transpose x [b][t][i] -> g_xT [t][i][b]
// ============================================================
__global__ void __launch_bounds__(256) xpose_kernel(const float* __restrict__ x)
{
    __shared__ float xs[BB * (II + 1)];
    const int t = blockIdx.x;
    for (int idx = threadIdx.x; idx < BB * II; idx += 256) {
        int b = idx >> 7, i = idx & 127;
        xs[b * (II + 1) + i] = x[((size_t)b * TT + t) * II + i];
    }
    __syncthreads();
    float* dst = g_xT + (size_t)t * (II * BB);
    for (int idx = threadIdx.x; idx < II * BB; idx += 256) {
        int i = idx >> 6, b = idx & 63;
        dst[idx] = xs[b * (II + 1) + i];
    }
}

// ============================================================
// Kernel 2: precompute gx[t][b][j][g] = (x_t . W_x)
// ============================================================
#define GX_XS 0
#define GX_WS (II * HXS)
#define GX_SMEM_FLOATS (GX_WS + II * 128)
#define GX_SMEM_BYTES  (GX_SMEM_FLOATS * 4)

__global__ void __launch_bounds__(512) gx_kernel(const float* __restrict__ Wx)
{
    extern __shared__ float sm[];
    float* xs  = sm + GX_XS;
    float* ws2 = sm + GX_WS;

    const int t    = blockIdx.x;
    const int cb   = blockIdx.y;
    const int tid  = threadIdx.x;
    const int lane = tid & 31;
    const int bq   = tid >> 5;

    {
        const float* src = g_xT + (size_t)t * (II * BB);
        #pragma unroll
        for (int i = 0; i < 4; ++i) {
            int idx = tid + i * 512;
            int row = idx >> 4, c4 = (idx & 15) << 2;
            cp16(xs + row * HXS + c4, src + idx * 4);
        }
        CP_COMMIT();
    }
    #pragma unroll
    for (int j = 0; j < 32; ++j) {
        int idx = tid + j * 512;
        int k = idx >> 7, rem = idx & 127;
        int g = rem >> 5, hl = rem & 31;
        ws2[k * 128 + hl * 4 + g] = __ldg(Wx + ((size_t)g * II + k) * HH + (cb << 5) + hl);
    }
    CP_WAIT0();
    __syncthreads();

    ull acc2[8];
    #pragma unroll
    for (int i = 0; i < 8; ++i) acc2[i] = 0ull;

    const float* xp = xs + (bq << 2);
    const float* wp = ws2 + (lane << 2);
    #pragma unroll 4
    for (int k = 0; k < II; ++k) {
        float4 hv = *(const float4*)(xp + k * HXS);
        ulonglong2 wv = *(const ulonglong2*)(wp + k * 128);
        ull h0 = pk2(hv.x), h1 = pk2(hv.y), h2 = pk2(hv.z), h3 = pk2(hv.w);
        fma2(acc2[0], h0, wv.x); fma2(acc2[1], h0, wv.y);
        fma2(acc2[2], h1, wv.x); fma2(acc2[3], h1, wv.y);
        fma2(acc2[4], h2, wv.x); fma2(acc2[5], h2, wv.y);
        fma2(acc2[6], h3, wv.x); fma2(acc2[7], h3, wv.y);
    }

    #pragma unroll
    for (int r = 0; r < 4; ++r) {
        int b = (bq << 2) + r;
        ulonglong2 v; v.x = acc2[r * 2]; v.y = acc2[r * 2 + 1];
        *(ulonglong2*)(g_gx + (((size_t)t * BB + b) * HH + (cb << 5) + lane) * 4) = v;
    }
}

// ============================================================
// Kernel 3: clustered LSTM, 1024 threads (occ 50%).
// 16 clusters x 8 CTAs; cluster cid owns batches 4cid..4cid+3.
// CTA rank r owns j in [32r, 32r+32) (local col = jl*4 + g).
// Warp w<16: cols 8w..8w+7, k in [0,128). Warp w+16: same cols, k in [128,256).
// Lane: k-sub-slice {kbase+lane+32u, u<4}. Butterfly -> 1 output/lane (half-sum).
// Upper half writes red[], lower half combines + cell + DSMEM fan-out.
// SMEM: ws[256][132] @0, hb[2][256][4] @33792, red[512] @35840.
// ============================================================
#define SM_HB (HH * WST)                   /* 33792 */
#define SM_RED (SM_HB + 2 * HH * 4)        /* 35840 */
#define SMEM_FLOATS (SM_RED + 512)
#define SMEM_BYTES  (SMEM_FLOATS * 4)

__global__ void __launch_bounds__(NTHR, 1) __cluster_dims__(CLUS, 1, 1)
lstm_kernel(const float* __restrict__ Wh, const float* __restrict__ bias,
            float* __restrict__ out)
{
    extern __shared__ float sm[];
    float* ws  = sm;
    float* hb  = sm + SM_HB;
    float* red = sm + SM_RED;

    const int tid  = threadIdx.x;
    const int w    = tid >> 5;
    const int lane = tid & 31;
    const int wl   = w & 15;          // column-group id
    const int kh   = w >> 4;          // k-half: 0 => k<128, 1 => k>=128
    unsigned rank;
    asm("mov.u32 %0, %%cluster_ctarank;" : "=r"(rank));
    const int cid = blockIdx.x >> 3;

    // one-time: W_h slice ws[k*132 + jl*4 + g] = Wh[g][k][32r + jl]
    for (int idx = tid; idx < HH * 128; idx += NTHR) {
        int k = idx >> 7, rem = idx & 127;
        int g = rem >> 5, jl = rem & 31;
        ws[k * WST + jl * 4 + g] =
            __ldg(Wh + ((size_t)g * HH + k) * HH + (rank << 5) + jl);
    }

    const int  col  = (wl << 3) + (lane & 7);
    const int  b_l  = lane >> 3;
    const int  j    = (int)(rank << 5) + (col >> 2);
    const int  gg_  = col & 3;
    const int  bse  = lane & 28;
    const bool low  = (kh == 0);
    const bool upd  = low && ((lane & 3) == 0);
    const float biasv = low ? __ldg(bias + (size_t)gg_ * HH + j) : 0.f;
    const int  myb  = (cid << 2) + b_l;
    const float* gxp = g_gx + (((size_t)myb * HH + j) << 2) + gg_;

    const unsigned hb_u = smem_u32(hb);
    const int kbase = kh << 7;
    float creg = 0.f;

    __syncthreads();   // ws ready

    for (int t = 0; t < TT; ++t) {
        float gxv = low ? __ldg(gxp + (size_t)t * (BB * HH * 4)) : 0.f;

        ull acc2[16];
        #pragma unroll
        for (int i = 0; i < 16; ++i) acc2[i] = 0ull;

        if (t > 0) {
            CLUSTER_WAIT();   // acquire: h_{t-1} visible in hb[t&1]
            const float* hbr = hb + ((t & 1) << 10);
            const float* wsw = ws + (wl << 3);
            #pragma unroll
            for (int u = 0; u < 4; ++u) {
                const int k = kbase + lane + (u << 5);
                float4 hv = *(const float4*)(hbr + (k << 2));
                ulonglong2 w0 = *(const ulonglong2*)(wsw + k * WST);
                ulonglong2 w1 = *(const ulonglong2*)(wsw + k * WST + 4);
                ull h0 = pk2(hv.x), h1 = pk2(hv.y), h2 = pk2(hv.z), h3 = pk2(hv.w);
                fma2(acc2[0],  h0, w0.x); fma2(acc2[1],  h0, w0.y);
                fma2(acc2[2],  h0, w1.x); fma2(acc2[3],  h0, w1.y);
                fma2(acc2[4],  h1, w0.x); fma2(acc2[5],  h1, w0.y);
                fma2(acc2[6],  h1, w1.x); fma2(acc2[7],  h1, w1.y);
                fma2(acc2[8],  h2, w0.x); fma2(acc2[9],  h2, w0.y);
                fma2(acc2[10], h2, w1.x); fma2(acc2[11], h2, w1.y);
                fma2(acc2[12], h3, w0.x); fma2(acc2[13], h3, w0.y);
                fma2(acc2[14], h3, w1.x); fma2(acc2[15], h3, w1.y);
            }
        }

        // packed butterfly reduce-scatter: lane l <- half-sum of output
        // (b = l>>3, col = 8wl + (l&7))
        #pragma unroll
        for (int n = 16; n >= 2; n >>= 1) {
            const int m = n >> 1;
            #pragma unroll
            for (int s = 0; s < m; ++s) {
                ull lo = acc2[s], hi = acc2[s + m];
                ull send = (lane & n) ? lo : hi;
                ull keep = (lane & n) ? hi : lo;
                acc2[s] = add2(keep, __shfl_xor_sync(0xffffffffu, send, n));
            }
        }
        float pre;
        {
            unsigned u0, u1;
            asm("mov.b64 {%0, %1}, %2;" : "=r"(u0), "=r"(u1) : "l"(acc2[0]));
            float a0 = __uint_as_float(u0), a1 = __uint_as_float(u1);
            float send = (lane & 1) ? a0 : a1;
            float keep = (lane & 1) ? a1 : a0;
            pre = keep + __shfl_xor_sync(0xffffffffu, send, 1);
        }

        // ---- combine k-halves: upper warps publish, lower warps consume ----
        if (!low) red[(wl << 5) + lane] = pre;
        __syncthreads();
        if (low) pre += red[(wl << 5) + lane] + gxv + biasv;

        // gather 4 gates (cols jl*4+0..3 at lanes bse..bse+3), cell update
        float pf = __shfl_sync(0xffffffffu, pre, bse | 1);
        float pg = __shfl_sync(0xffffffffu, pre, bse | 2);
        float po = __shfl_sync(0xffffffffu, pre, bse | 3);
        if (upd) {
            float ig = 1.f / (1.f + __expf(-pre));
            float fg = 1.f / (1.f + __expf(-pf));
            float gv = tanhf(pg);
            float og = 1.f / (1.f + __expf(-po));
            creg = fg * creg + ig * gv;
            float hv = og * tanhf(creg);
            if (t + 1 < TT) {
                unsigned off = ((unsigned)((t & 1) ^ 1) << 12)
                             + (unsigned)j * 16 + ((unsigned)b_l << 2);
                #pragma unroll
                for (int r = 0; r < CLUS; ++r) {
                    unsigned ra = mapa_rank(hb_u, (unsigned)r) + off;
                    asm volatile("st.shared::cluster.f32 [%0], %1;"
                                 :: "r"(ra), "f"(hv) : "memory");
                }
            }
            out[((size_t)myb * TT + t) * HH + j] = hv;
        }

        CLUSTER_ARRIVE();   // release: h_t visible to peers after their wait
    }
    CLUSTER_WAIT();         // matches final arrive; no early exit
}

// ============================================================
extern "C" void kernel_launch(void* const* d_in, const int* in_sizes, int n_in,
                              void* d_out, int out_size)
{
    const float* x  = (const float*)d_in[0];   // [B, T, I]
    const float* Wx = (const float*)d_in[1];   // [4, I, H]
    const float* Wh = (const float*)d_in[2];   // [4, H, H]
    const float* b  = (const float*)d_in[3];   // [4, H]
    float* out = (float*)d_out;                // [B, T, H]

    cudaFuncSetAttribute(gx_kernel,
                         cudaFuncAttributeMaxDynamicSharedMemorySize, GX_SMEM_BYTES);
    cudaFuncSetAttribute(lstm_kernel,
                         cudaFuncAttributeMaxDynamicSharedMemorySize, SMEM_BYTES);

    xpose_kernel<<<TT, 256>>>(x);
    gx_kernel<<<dim3(TT, 8), 512, GX_SMEM_BYTES>>>(Wx);
    lstm_kernel<<<NBLK, NTHR, SMEM_BYTES>>>(Wh, b, out);
}

// round 9
// speedup vs baseline: 1.2307x; 1.0062x over previous
#include <cuda_runtime.h>
#include <math.h>

typedef unsigned long long ull;

#define TT 2048
#define BB 64
#define II 128
#define HH 256
#define NBLK 128            /* 16 clusters x 8 CTAs */
#define CLUS 8
#define NTHR 512
#define HXS  68             /* gx-kernel x staging row stride */
#define WST  132            /* W_h slice row stride (128 cols + 4 pad) */

// ---- device scratch (static) ----
__device__ __align__(16) float g_xT[(size_t)TT * II * BB];       // [t][i][b]
__device__ __align__(16) float g_gx[(size_t)TT * BB * HH * 4];   // [t][b][j][g]

// ---- helpers ----
__device__ __forceinline__ void cp16(float* smem_dst, const float* gmem_src) {
    unsigned s = (unsigned)__cvta_generic_to_shared(smem_dst);
    asm volatile("cp.async.cg.shared.global [%0], [%1], 16;" :: "r"(s), "l"(gmem_src));
}
#define CP_COMMIT() asm volatile("cp.async.commit_group;" ::: "memory")
#define CP_WAIT0()  asm volatile("cp.async.wait_group 0;" ::: "memory")

__device__ __forceinline__ ull pk2(float v) {
    ull r; unsigned u = __float_as_uint(v);
    asm("mov.b64 %0, {%1, %1};" : "=l"(r) : "r"(u));
    return r;
}
__device__ __forceinline__ ull pkab(float a, float b) {
    ull r; unsigned ua = __float_as_uint(a), ub = __float_as_uint(b);
    asm("mov.b64 %0, {%1, %2};" : "=l"(r) : "r"(ua), "r"(ub));
    return r;
}
__device__ __forceinline__ void fma2(ull& d, ull a, ull b) {
    asm("fma.rn.f32x2 %0, %1, %2, %0;" : "+l"(d) : "l"(a), "l"(b));
}
__device__ __forceinline__ ull add2(ull a, ull b) {
    ull r; asm("add.rn.f32x2 %0, %1, %2;" : "=l"(r) : "l"(a), "l"(b));
    return r;
}
__device__ __forceinline__ float tanh_ap(float x) {
    float y; asm("tanh.approx.f32 %0, %1;" : "=f"(y) : "f"(x));
    return y;
}
__device__ __forceinline__ float sig_ap(float x) {
    return fmaf(0.5f, tanh_ap(0.5f * x), 0.5f);
}
__device__ __forceinline__ unsigned smem_u32(const void* p) {
    unsigned a;
    asm("{ .reg .u64 t; cvta.to.shared.u64 t, %1; cvt.u32.u64 %0, t; }"
        : "=r"(a) : "l"(p));
    return a;
}
__device__ __forceinline__ unsigned mapa_rank(unsigned laddr, unsigned rank) {
    unsigned r;
    asm("mapa.shared::cluster.u32 %0, %1, %2;" : "=r"(r) : "r"(laddr), "r"(rank));
    return r;
}
#define CLUSTER_ARRIVE() asm volatile("barrier.cluster.arrive.aligned;" ::: "memory")
#define CLUSTER_WAIT()   asm volatile("barrier.cluster.wait.aligned;" ::: "memory")

// ============================================================
// Kernel 1: transpose x [b][t][i] -> g_xT [t][i][b]
// ============================================================
__global__ void __launch_bounds__(256) xpose_kernel(const float* __restrict__ x)
{
    __shared__ float xs[BB * (II + 1)];
    const int t = blockIdx.x;
    for (int idx = threadIdx.x; idx < BB * II; idx += 256) {
        int b = idx >> 7, i = idx & 127;
        xs[b * (II + 1) + i] = x[((size_t)b * TT + t) * II + i];
    }
    __syncthreads();
    float* dst = g_xT + (size_t)t * (II * BB);
    for (int idx = threadIdx.x; idx < II * BB; idx += 256) {
        int i = idx >> 6, b = idx & 63;
        dst[idx] = xs[b * (II + 1) + i];
    }
}

// ============================================================
// Kernel 2: precompute gx[t][b][j][g] = (x_t . W_x)
// ============================================================
#define GX_XS 0
#define GX_WS (II * HXS)
#define GX_SMEM_FLOATS (GX_WS + II * 128)
#define GX_SMEM_BYTES  (GX_SMEM_FLOATS * 4)

__global__ void __launch_bounds__(512) gx_kernel(const float* __restrict__ Wx)
{
    extern __shared__ float sm[];
    float* xs  = sm + GX_XS;
    float* ws2 = sm + GX_WS;

    const int t    = blockIdx.x;
    const int cb   = blockIdx.y;
    const int tid  = threadIdx.x;
    const int lane = tid & 31;
    const int bq   = tid >> 5;

    {
        const float* src = g_xT + (size_t)t * (II * BB);
        #pragma unroll
        for (int i = 0; i < 4; ++i) {
            int idx = tid + i * 512;
            int row = idx >> 4, c4 = (idx & 15) << 2;
            cp16(xs + row * HXS + c4, src + idx * 4);
        }
        CP_COMMIT();
    }
    #pragma unroll
    for (int j = 0; j < 32; ++j) {
        int idx = tid + j * 512;
        int k = idx >> 7, rem = idx & 127;
        int g = rem >> 5, hl = rem & 31;
        ws2[k * 128 + hl * 4 + g] = __ldg(Wx + ((size_t)g * II + k) * HH + (cb << 5) + hl);
    }
    CP_WAIT0();
    __syncthreads();

    ull acc2[8];
    #pragma unroll
    for (int i = 0; i < 8; ++i) acc2[i] = 0ull;

    const float* xp = xs + (bq << 2);
    const float* wp = ws2 + (lane << 2);
    #pragma unroll 4
    for (int k = 0; k < II; ++k) {
        float4 hv = *(const float4*)(xp + k * HXS);
        ulonglong2 wv = *(const ulonglong2*)(wp + k * 128);
        ull h0 = pk2(hv.x), h1 = pk2(hv.y), h2 = pk2(hv.z), h3 = pk2(hv.w);
        fma2(acc2[0], h0, wv.x); fma2(acc2[1], h0, wv.y);
        fma2(acc2[2], h1, wv.x); fma2(acc2[3], h1, wv.y);
        fma2(acc2[4], h2, wv.x); fma2(acc2[5], h2, wv.y);
        fma2(acc2[6], h3, wv.x); fma2(acc2[7], h3, wv.y);
    }

    #pragma unroll
    for (int r = 0; r < 4; ++r) {
        int b = (bq << 2) + r;
        ulonglong2 v; v.x = acc2[r * 2]; v.y = acc2[r * 2 + 1];
        *(ulonglong2*)(g_gx + (((size_t)t * BB + b) * HH + (cb << 5) + lane) * 4) = v;
    }
}

// ============================================================
// Kernel 3: clustered LSTM (R6 structure).
// 16 clusters x 8 CTAs; cluster cid owns batches 4cid..4cid+3.
// CTA rank r owns j in [32r, 32r+32) (local col = jl*4 + g).
// Warp w: cols 8w..8w+7, all 4 batches. Lane: k-slice {lane+32u}.
// W_h for k<128 in registers (wregA); k>=128 in SMEM.
// SMEM: ws[128][132] @0 (rows k=128..255), hb[2][256][4] @16896.
// ============================================================
#define SM_HB (128 * WST)                  /* 16896 floats */
#define SMEM_FLOATS (SM_HB + 2 * HH * 4)
#define SMEM_BYTES  (SMEM_FLOATS * 4)

__global__ void __launch_bounds__(NTHR, 1) __cluster_dims__(CLUS, 1, 1)
lstm_kernel(const float* __restrict__ Wh, const float* __restrict__ bias,
            float* __restrict__ out)
{
    extern __shared__ float sm[];
    float* ws = sm;                  // W_h rows k = 128..255
    float* hb = sm + SM_HB;

    const int tid  = threadIdx.x;
    const int w    = tid >> 5;
    const int lane = tid & 31;
    unsigned rank;
    asm("mov.u32 %0, %%cluster_ctarank;" : "=r"(rank));
    const int cid = blockIdx.x >> 3;

    // one-time: W_h upper half into SMEM: ws[(k-128)*132 + jl*4 + g]
    for (int idx = tid; idx < 128 * 128; idx += NTHR) {
        int kr = idx >> 7, rem = idx & 127;
        int g = rem >> 5, jl = rem & 31;
        ws[kr * WST + jl * 4 + g] =
            __ldg(Wh + ((size_t)g * HH + (128 + kr)) * HH + (rank << 5) + jl);
    }

    // one-time: W_h lower half (k = lane+32u, u<4) into registers, packed
    // col-pairs matching acc2 layout: wregA[u*4+p] = (col 2p, col 2p+1) of
    // this warp's 8-col group.
    ull wregA[16];
    #pragma unroll
    for (int u = 0; u < 4; ++u) {
        const int k = lane + (u << 5);
        #pragma unroll
        for (int p = 0; p < 4; ++p) {
            const int c0 = (w << 3) + (p << 1), c1 = c0 + 1;
            float f0 = __ldg(Wh + ((size_t)(c0 & 3) * HH + k) * HH + (rank << 5) + (c0 >> 2));
            float f1 = __ldg(Wh + ((size_t)(c1 & 3) * HH + k) * HH + (rank << 5) + (c1 >> 2));
            wregA[(u << 2) + p] = pkab(f0, f1);
        }
    }

    const int  col  = (w << 3) + (lane & 7);
    const int  b_l  = lane >> 3;
    const int  j    = (int)(rank << 5) + (col >> 2);
    const int  gg_  = col & 3;
    const int  bse  = lane & 28;
    const bool upd  = (lane & 3) == 0;
    const float biasv = __ldg(bias + (size_t)gg_ * HH + j);
    const int  myb  = (cid << 2) + b_l;
    const float* gxp = g_gx + (((size_t)myb * HH + j) << 2) + gg_;

    const unsigned hb_u = smem_u32(hb);
    float creg = 0.f;

    __syncthreads();   // ws ready

    for (int t = 0; t < TT; ++t) {
        float gxv = __ldg(gxp + (size_t)t * (BB * HH * 4));

        ull acc2[16];
        #pragma unroll
        for (int i = 0; i < 16; ++i) acc2[i] = 0ull;

        if (t > 0) {
            CLUSTER_WAIT();   // acquire: h_{t-1} visible in hb[t&1]
            const float* hbr = hb + ((t & 1) << 10);
            // ---- k < 128: weights from registers ----
            #pragma unroll
            for (int u = 0; u < 4; ++u) {
                const int k = lane + (u << 5);
                float4 hv = *(const float4*)(hbr + (k << 2));
                ull h0 = pk2(hv.x), h1 = pk2(hv.y), h2 = pk2(hv.z), h3 = pk2(hv.w);
                const int ub = u << 2;
                fma2(acc2[0],  h0, wregA[ub + 0]); fma2(acc2[1],  h0, wregA[ub + 1]);
                fma2(acc2[2],  h0, wregA[ub + 2]); fma2(acc2[3],  h0, wregA[ub + 3]);
                fma2(acc2[4],  h1, wregA[ub + 0]); fma2(acc2[5],  h1, wregA[ub + 1]);
                fma2(acc2[6],  h1, wregA[ub + 2]); fma2(acc2[7],  h1, wregA[ub + 3]);
                fma2(acc2[8],  h2, wregA[ub + 0]); fma2(acc2[9],  h2, wregA[ub + 1]);
                fma2(acc2[10], h2, wregA[ub + 2]); fma2(acc2[11], h2, wregA[ub + 3]);
                fma2(acc2[12], h3, wregA[ub + 0]); fma2(acc2[13], h3, wregA[ub + 1]);
                fma2(acc2[14], h3, wregA[ub + 2]); fma2(acc2[15], h3, wregA[ub + 3]);
            }
            // ---- k >= 128: weights from SMEM ----
            const float* wsw = ws + (w << 3);
            #pragma unroll
            for (int u = 4; u < 8; ++u) {
                const int k = lane + (u << 5);
                float4 hv = *(const float4*)(hbr + (k << 2));
                ulonglong2 w0 = *(const ulonglong2*)(wsw + (k - 128) * WST);
                ulonglong2 w1 = *(const ulonglong2*)(wsw + (k - 128) * WST + 4);
                ull h0 = pk2(hv.x), h1 = pk2(hv.y), h2 = pk2(hv.z), h3 = pk2(hv.w);
                fma2(acc2[0],  h0, w0.x); fma2(acc2[1],  h0, w0.y);
                fma2(acc2[2],  h0, w1.x); fma2(acc2[3],  h0, w1.y);
                fma2(acc2[4],  h1, w0.x); fma2(acc2[5],  h1, w0.y);
                fma2(acc2[6],  h1, w1.x); fma2(acc2[7],  h1, w1.y);
                fma2(acc2[8],  h2, w0.x); fma2(acc2[9],  h2, w0.y);
                fma2(acc2[10], h2, w1.x); fma2(acc2[11], h2, w1.y);
                fma2(acc2[12], h3, w0.x); fma2(acc2[13], h3, w0.y);
                fma2(acc2[14], h3, w1.x); fma2(acc2[15], h3, w1.y);
            }
        }

        // packed butterfly reduce-scatter: lane l <- output (b=l>>3, col=8w+(l&7))
        #pragma unroll
        for (int n = 16; n >= 2; n >>= 1) {
            const int m = n >> 1;
            #pragma unroll
            for (int s = 0; s < m; ++s) {
                ull lo = acc2[s], hi = acc2[s + m];
                ull send = (lane & n) ? lo : hi;
                ull keep = (lane & n) ? hi : lo;
                acc2[s] = add2(keep, __shfl_xor_sync(0xffffffffu, send, n));
            }
        }
        float pre;
        {
            unsigned u0, u1;
            asm("mov.b64 {%0, %1}, %2;" : "=r"(u0), "=r"(u1) : "l"(acc2[0]));
            float a0 = __uint_as_float(u0), a1 = __uint_as_float(u1);
            float send = (lane & 1) ? a0 : a1;
            float keep = (lane & 1) ? a1 : a0;
            pre = keep + __shfl_xor_sync(0xffffffffu, send, 1);
        }
        pre += gxv + biasv;

        // gather 4 gates (cols jl*4+0..3 live at lanes bse..bse+3)
        float pf = __shfl_sync(0xffffffffu, pre, bse | 1);
        float pg = __shfl_sync(0xffffffffu, pre, bse | 2);
        float po = __shfl_sync(0xffffffffu, pre, bse | 3);
        float hv_out = 0.f;
        if (upd) {
            float ig = sig_ap(pre);
            float fg = sig_ap(pf);
            float gv = tanh_ap(pg);
            float og = sig_ap(po);
            creg = fg * creg + ig * gv;
            hv_out = og * tanh_ap(creg);
            if (t + 1 < TT) {
                unsigned off = ((unsigned)((t & 1) ^ 1) << 12)
                             + (unsigned)j * 16 + ((unsigned)b_l << 2);
                #pragma unroll
                for (int r = 0; r < CLUS; ++r) {
                    unsigned ra = mapa_rank(hb_u, (unsigned)r) + off;
                    asm volatile("st.shared::cluster.f32 [%0], %1;"
                                 :: "r"(ra), "f"(hv_out) : "memory");
                }
            }
        }

        CLUSTER_ARRIVE();   // release: h_t visible to peers after their wait

        if (upd)            // off the inter-CTA critical path
            out[((size_t)myb * TT + t) * HH + j] = hv_out;
    }
    CLUSTER_WAIT();         // matches final arrive; no early exit
}

// ============================================================
extern "C" void kernel_launch(void* const* d_in, const int* in_sizes, int n_in,
                              void* d_out, int out_size)
{
    const float* x  = (const float*)d_in[0];   // [B, T, I]
    const float* Wx = (const float*)d_in[1];   // [4, I, H]
    const float* Wh = (const float*)d_in[2];   // [4, H, H]
    const float* b  = (const float*)d_in[3];   // [4, H]
    float* out = (float*)d_out;                // [B, T, H]

    cudaFuncSetAttribute(gx_kernel,
                         cudaFuncAttributeMaxDynamicSharedMemorySize, GX_SMEM_BYTES);
    cudaFuncSetAttribute(lstm_kernel,
                         cudaFuncAttributeMaxDynamicSharedMemorySize, SMEM_BYTES);

    xpose_kernel<<<TT, 256>>>(x);
    gx_kernel<<<dim3(TT, 8), 512, GX_SMEM_BYTES>>>(Wx);
    lstm_kernel<<<NBLK, NTHR, SMEM_BYTES>>>(Wh, b, out);
}

// round 10
// speedup vs baseline: 1.8692x; 1.5189x over previous
#include <cuda_runtime.h>
#include <math.h>

typedef unsigned long long ull;

#define TT 2048
#define BB 64
#define II 128
#define HH 256
#define NBLK 128            /* 16 clusters x 8 CTAs */
#define CLUS 8
#define NTHR 512
#define HXS  68             /* gx-kernel x staging row stride */
#define WST  132            /* W_h slice row stride (128 cols + 4 pad) */

// ---- device scratch (static) ----
__device__ __align__(16) float g_gx[(size_t)TT * BB * HH * 4];   // [t][b][j][g]

// ---- helpers ----
__device__ __forceinline__ ull pk2(float v) {
    ull r; unsigned u = __float_as_uint(v);
    asm("mov.b64 %0, {%1, %1};" : "=l"(r) : "r"(u));
    return r;
}
__device__ __forceinline__ void fma2(ull& d, ull a, ull b) {
    asm("fma.rn.f32x2 %0, %1, %2, %0;" : "+l"(d) : "l"(a), "l"(b));
}
__device__ __forceinline__ ull add2(ull a, ull b) {
    ull r; asm("add.rn.f32x2 %0, %1, %2;" : "=l"(r) : "l"(a), "l"(b));
    return r;
}
__device__ __forceinline__ float tanh_ap(float x) {
    float y; asm("tanh.approx.f32 %0, %1;" : "=f"(y) : "f"(x));
    return y;
}
__device__ __forceinline__ float sig_ap(float x) {
    return fmaf(0.5f, tanh_ap(0.5f * x), 0.5f);
}
__device__ __forceinline__ unsigned smem_u32(const void* p) {
    unsigned a;
    asm("{ .reg .u64 t; cvta.to.shared.u64 t, %1; cvt.u32.u64 %0, t; }"
        : "=r"(a) : "l"(p));
    return a;
}
__device__ __forceinline__ unsigned mapa_rank(unsigned laddr, unsigned rank) {
    unsigned r;
    asm("mapa.shared::cluster.u32 %0, %1, %2;" : "=r"(r) : "r"(laddr), "r"(rank));
    return r;
}
#define CLUSTER_ARRIVE() asm volatile("barrier.cluster.arrive.aligned;" ::: "memory")
#define CLUSTER_WAIT()   asm volatile("barrier.cluster.wait.aligned;" ::: "memory")

// ============================================================
// Kernel 1: precompute gx[t][b][j][g] = (x_t . W_x), transpose fused.
// grid (t=2048, cb=8): cb covers h-cols 32cb..32cb+31 (x 4 gates).
// ============================================================
#define GX_XS 0
#define GX_WS (II * HXS)
#define GX_SMEM_FLOATS (GX_WS + II * 128)
#define GX_SMEM_BYTES  (GX_SMEM_FLOATS * 4)

__global__ void __launch_bounds__(512) gx_kernel(const float* __restrict__ x,
                                                 const float* __restrict__ Wx)
{
    extern __shared__ float sm[];
    float* xs  = sm + GX_XS;    // xs[i*68 + b]
    float* ws2 = sm + GX_WS;    // ws2[k*128 + hl*4 + g]

    const int t    = blockIdx.x;
    const int cb   = blockIdx.y;
    const int tid  = threadIdx.x;
    const int lane = tid & 31;
    const int bq   = tid >> 5;

    // load + transpose x_t directly from x[b][t][i] (coalesced over i)
    #pragma unroll
    for (int jj = 0; jj < 16; ++jj) {
        int idx = tid + jj * 512;
        int b = idx >> 7, i = idx & 127;
        xs[i * HXS + b] = __ldg(x + ((size_t)b * TT + t) * II + i);
    }
    // weight slice
    #pragma unroll
    for (int jj = 0; jj < 32; ++jj) {
        int idx = tid + jj * 512;
        int k = idx >> 7, rem = idx & 127;
        int g = rem >> 5, hl = rem & 31;
        ws2[k * 128 + hl * 4 + g] = __ldg(Wx + ((size_t)g * II + k) * HH + (cb << 5) + hl);
    }
    __syncthreads();

    ull acc2[8];
    #pragma unroll
    for (int i = 0; i < 8; ++i) acc2[i] = 0ull;

    const float* xp = xs + (bq << 2);
    const float* wp = ws2 + (lane << 2);
    #pragma unroll 4
    for (int k = 0; k < II; ++k) {
        float4 hv = *(const float4*)(xp + k * HXS);
        ulonglong2 wv = *(const ulonglong2*)(wp + k * 128);
        ull h0 = pk2(hv.x), h1 = pk2(hv.y), h2 = pk2(hv.z), h3 = pk2(hv.w);
        fma2(acc2[0], h0, wv.x); fma2(acc2[1], h0, wv.y);
        fma2(acc2[2], h1, wv.x); fma2(acc2[3], h1, wv.y);
        fma2(acc2[4], h2, wv.x); fma2(acc2[5], h2, wv.y);
        fma2(acc2[6], h3, wv.x); fma2(acc2[7], h3, wv.y);
    }

    // thread covers j = 32cb + lane, gates 0..3, batches 4bq..4bq+3
    #pragma unroll
    for (int r = 0; r < 4; ++r) {
        int b = (bq << 2) + r;
        ulonglong2 v; v.x = acc2[r * 2]; v.y = acc2[r * 2 + 1];
        *(ulonglong2*)(g_gx + (((size_t)t * BB + b) * HH + (cb << 5) + lane) * 4) = v;
    }
}

// ============================================================
// Kernel 2: clustered LSTM recurrence (exact R6 structure).
// 16 clusters x 8 CTAs; cluster cid owns batches 4cid..4cid+3.
// CTA rank r owns j in [32r, 32r+32) (local col = jl*4 + g).
// Warp w: cols 8w..8w+7, all 4 batches. Lane: k-slice {lane+32u}.
// h exchanged via DSMEM stores + barrier.cluster per step.
// SMEM: ws[256][132] @0, hb[2][256][4] @33792
// ============================================================
#define SM_HB (HH * WST)
#define SMEM_FLOATS (SM_HB + 2 * HH * 4)
#define SMEM_BYTES  (SMEM_FLOATS * 4)

__global__ void __launch_bounds__(NTHR, 1) __cluster_dims__(CLUS, 1, 1)
lstm_kernel(const float* __restrict__ Wh, const float* __restrict__ bias,
            float* __restrict__ out)
{
    extern __shared__ float sm[];
    float* ws = sm;
    float* hb = sm + SM_HB;

    const int tid  = threadIdx.x;
    const int w    = tid >> 5;
    const int lane = tid & 31;
    unsigned rank;
    asm("mov.u32 %0, %%cluster_ctarank;" : "=r"(rank));
    const int cid = blockIdx.x >> 3;

    // one-time: W_h slice ws[k*132 + jl*4 + g] = Wh[g][k][32r + jl]
    for (int idx = tid; idx < HH * 128; idx += NTHR) {
        int k = idx >> 7, rem = idx & 127;
        int g = rem >> 5, jl = rem & 31;
        ws[k * WST + jl * 4 + g] =
            __ldg(Wh + ((size_t)g * HH + k) * HH + (rank << 5) + jl);
    }

    const int  col  = (w << 3) + (lane & 7);
    const int  b_l  = lane >> 3;
    const int  j    = (int)(rank << 5) + (col >> 2);
    const int  gg_  = col & 3;
    const int  bse  = lane & 28;
    const bool upd  = (lane & 3) == 0;
    const float biasv = __ldg(bias + (size_t)gg_ * HH + j);
    const int  myb  = (cid << 2) + b_l;
    const float* gxp = g_gx + (((size_t)myb * HH + j) << 2) + gg_;

    // hoisted: 8 remote hb base addresses (loop-invariant)
    const unsigned hb_u = smem_u32(hb);
    unsigned rb[CLUS];
    #pragma unroll
    for (int r = 0; r < CLUS; ++r) rb[r] = mapa_rank(hb_u, (unsigned)r);
    const unsigned joff = (unsigned)j * 16 + ((unsigned)b_l << 2);

    float creg = 0.f;
    __syncthreads();   // ws ready

    for (int t = 0; t < TT; ++t) {
        float gxv = __ldg(gxp + (size_t)t * (BB * HH * 4));  // issued before wait

        ull acc2[16];
        #pragma unroll
        for (int i = 0; i < 16; ++i) acc2[i] = 0ull;

        if (t > 0) {
            CLUSTER_WAIT();   // acquire: h_{t-1} visible in hb[t&1]
            const float* hbr = hb + ((t & 1) << 10);
            const float* wsw = ws + (w << 3);
            #pragma unroll
            for (int u = 0; u < 8; ++u) {
                const int k = lane + (u << 5);
                float4 hv = *(const float4*)(hbr + (k << 2));
                ulonglong2 w0 = *(const ulonglong2*)(wsw + k * WST);
                ulonglong2 w1 = *(const ulonglong2*)(wsw + k * WST + 4);
                ull h0 = pk2(hv.x), h1 = pk2(hv.y), h2 = pk2(hv.z), h3 = pk2(hv.w);
                fma2(acc2[0],  h0, w0.x); fma2(acc2[1],  h0, w0.y);
                fma2(acc2[2],  h0, w1.x); fma2(acc2[3],  h0, w1.y);
                fma2(acc2[4],  h1, w0.x); fma2(acc2[5],  h1, w0.y);
                fma2(acc2[6],  h1, w1.x); fma2(acc2[7],  h1, w1.y);
                fma2(acc2[8],  h2, w0.x); fma2(acc2[9],  h2, w0.y);
                fma2(acc2[10], h2, w1.x); fma2(acc2[11], h2, w1.y);
                fma2(acc2[12], h3, w0.x); fma2(acc2[13], h3, w0.y);
                fma2(acc2[14], h3, w1.x); fma2(acc2[15], h3, w1.y);
            }
        }

        // packed butterfly reduce-scatter: lane l <- output (b=l>>3, col=8w+(l&7))
        #pragma unroll
        for (int n = 16; n >= 2; n >>= 1) {
            const int m = n >> 1;
            #pragma unroll
            for (int s = 0; s < m; ++s) {
                ull lo = acc2[s], hi = acc2[s + m];
                ull send = (lane & n) ? lo : hi;
                ull keep = (lane & n) ? hi : lo;
                acc2[s] = add2(keep, __shfl_xor_sync(0xffffffffu, send, n));
            }
        }
        float pre;
        {
            unsigned u0, u1;
            asm("mov.b64 {%0, %1}, %2;" : "=r"(u0), "=r"(u1) : "l"(acc2[0]));
            float a0 = __uint_as_float(u0), a1 = __uint_as_float(u1);
            float send = (lane & 1) ? a0 : a1;
            float keep = (lane & 1) ? a1 : a0;
            pre = keep + __shfl_xor_sync(0xffffffffu, send, 1);
        }
        pre += gxv + biasv;

        // gather 4 gates (cols jl*4+0..3 live at lanes bse..bse+3)
        float pf = __shfl_sync(0xffffffffu, pre, bse | 1);
        float pg = __shfl_sync(0xffffffffu, pre, bse | 2);
        float po = __shfl_sync(0xffffffffu, pre, bse | 3);
        float hv_out = 0.f;
        if (upd) {
            float ig = sig_ap(pre);
            float fg = sig_ap(pf);
            float gv = tanh_ap(pg);
            float og = sig_ap(po);
            creg = fg * creg + ig * gv;
            hv_out = og * tanh_ap(creg);
            if (t + 1 < TT) {
                unsigned off = ((unsigned)((t & 1) ^ 1) << 12) + joff;
                #pragma unroll
                for (int r = 0; r < CLUS; ++r) {
                    asm volatile("st.shared::cluster.f32 [%0], %1;"
                                 :: "r"(rb[r] + off), "f"(hv_out) : "memory");
                }
            }
        }

        CLUSTER_ARRIVE();   // release: h_t visible to peers after their wait

        if (upd)            // off the inter-CTA critical path
            out[((size_t)myb * TT + t) * HH + j] = hv_out;
    }
    CLUSTER_WAIT();         // matches final arrive; no early exit
}

// ============================================================
extern "C" void kernel_launch(void* const* d_in, const int* in_sizes, int n_in,
                              void* d_out, int out_size)
{
    const float* x  = (const float*)d_in[0];   // [B, T, I]
    const float* Wx = (const float*)d_in[1];   // [4, I, H]
    const float* Wh = (const float*)d_in[2];   // [4, H, H]
    const float* b  = (const float*)d_in[3];   // [4, H]
    float* out = (float*)d_out;                // [B, T, H]

    cudaFuncSetAttribute(gx_kernel,
                         cudaFuncAttributeMaxDynamicSharedMemorySize, GX_SMEM_BYTES);
    cudaFuncSetAttribute(lstm_kernel,
                         cudaFuncAttributeMaxDynamicSharedMemorySize, SMEM_BYTES);

    gx_kernel<<<dim3(TT, 8), 512, GX_SMEM_BYTES>>>(x, Wx);
    lstm_kernel<<<NBLK, NTHR, SMEM_BYTES>>>(Wh, b, out);
}